// round 1
// baseline (speedup 1.0000x reference)
#include <cuda_runtime.h>

// Problem constants (fixed by the dataset)
#define NN 50000
#define EE 800000

// ---------------- device scratch (no allocation allowed) ----------------
__device__ int   g_deg[NN];
__device__ int   g_roff[NN + 1];
__device__ int   g_cursor[NN];
__device__ int   g_csr[EE];
__device__ float g_xw[(size_t)NN * 128];   // XW scratch, reused per layer
__device__ float g_als[NN * 2];            // per-node src logits [N,H]
__device__ float g_ald[NN * 2];            // per-node dst logits [N,H]
__device__ float g_sum[128];
__device__ float g_sq[128];

// ---------------- small helpers ----------------
__device__ __forceinline__ unsigned long long pack2(float a, float b) {
    unsigned long long r;
    asm("mov.b64 %0, {%1, %2};" : "=l"(r) : "f"(a), "f"(b));
    return r;
}
__device__ __forceinline__ void fma2(unsigned long long& d, unsigned long long a, unsigned long long b) {
    asm("fma.rn.f32x2 %0, %1, %2, %0;" : "+l"(d) : "l"(a), "l"(b));
}
__device__ __forceinline__ float leaky(float v) { return v > 0.f ? v : 0.2f * v; }

// ---------------- CSR build ----------------
__global__ void k_zero_deg() {
    int i = blockIdx.x * blockDim.x + threadIdx.x;
    if (i < NN) g_deg[i] = 0;
}
__global__ void k_count(const int* __restrict__ dst, int e) {
    for (int i = blockIdx.x * blockDim.x + threadIdx.x; i < e; i += gridDim.x * blockDim.x)
        atomicAdd(&g_deg[dst[i]], 1);
}
__global__ void k_scan(int n) {
    __shared__ int part[1024];
    int tid = threadIdx.x;
    int chunk = (n + 1023) >> 10;
    int b0 = tid * chunk;
    int s = 0;
    for (int i = 0; i < chunk; i++) {
        int idx = b0 + i;
        if (idx < n) s += g_deg[idx];
    }
    part[tid] = s;
    __syncthreads();
    for (int off = 1; off < 1024; off <<= 1) {
        int v = (tid >= off) ? part[tid - off] : 0;
        __syncthreads();
        part[tid] += v;
        __syncthreads();
    }
    int run = (tid > 0) ? part[tid - 1] : 0;
    for (int i = 0; i < chunk; i++) {
        int idx = b0 + i;
        if (idx < n) {
            g_roff[idx] = run;
            g_cursor[idx] = run;
            run += g_deg[idx];
        }
    }
    if (tid == 1023) g_roff[n] = run;
}
__global__ void k_fill(const int* __restrict__ src, const int* __restrict__ dst, int e) {
    for (int i = blockIdx.x * blockDim.x + threadIdx.x; i < e; i += gridDim.x * blockDim.x) {
        int p = atomicAdd(&g_cursor[dst[i]], 1);
        g_csr[p] = src[i];
    }
}

// ---------------- GEMM: g_xw[n, COUT] = X[n, 0:128] @ W[128, COUT] ----------------
// block: 64 rows x COUT cols, 256 threads (16x16), thread tile 4 rows x (COUT/16) cols
// f32x2 packed FMA accumulators.
template <int COUT>
__launch_bounds__(256, 2)
__global__ void k_gemm(const float* __restrict__ X, int ldx, const float* __restrict__ W, int n) {
    constexpr int K = 128;
    constexpr int TC = COUT / 16;  // cols per thread: 8 or 4
    extern __shared__ float sm[];
    float* Ws = sm;                 // [K][COUT]
    float* Xs = sm + K * COUT;      // [64][K]
    int tid = threadIdx.x;
    int row0 = blockIdx.x * 64;

    // load W (K*COUT floats), fully coalesced float4
    {
        const float4* W4 = (const float4*)W;
        float4* Ws4 = (float4*)Ws;
        #pragma unroll
        for (int i = tid; i < K * COUT / 4; i += 256) Ws4[i] = W4[i];
    }
    // load X block rows (row-major in shared, coalesced)
    {
        #pragma unroll
        for (int i = tid; i < 64 * (K / 4); i += 256) {
            int r = i >> 5;            // K/4 = 32 float4 per row
            int kc = (i & 31) << 2;
            float4 v = make_float4(0.f, 0.f, 0.f, 0.f);
            if (row0 + r < n) v = *(const float4*)(X + (size_t)(row0 + r) * ldx + kc);
            *(float4*)(Xs + r * K + kc) = v;
        }
    }
    __syncthreads();

    int tx = tid & 15, ty = tid >> 4;
    unsigned long long acc[4][TC / 2];
    #pragma unroll
    for (int i = 0; i < 4; i++)
        #pragma unroll
        for (int j = 0; j < TC / 2; j++) acc[i][j] = 0ull;

    const float* xs0 = Xs + (ty * 4) * K;
    #pragma unroll 8
    for (int k = 0; k < K; k++) {
        unsigned long long xp[4];
        #pragma unroll
        for (int i = 0; i < 4; i++) {
            float xv = xs0[i * K + k];
            xp[i] = pack2(xv, xv);
        }
        const longlong2* wr = (const longlong2*)(Ws + k * COUT + tx * TC);
        #pragma unroll
        for (int jj = 0; jj < TC / 4; jj++) {
            longlong2 wv = wr[jj];
            #pragma unroll
            for (int i = 0; i < 4; i++) {
                fma2(acc[i][2 * jj], xp[i], (unsigned long long)wv.x);
                fma2(acc[i][2 * jj + 1], xp[i], (unsigned long long)wv.y);
            }
        }
    }
    #pragma unroll
    for (int i = 0; i < 4; i++) {
        int r = row0 + ty * 4 + i;
        if (r < n) {
            unsigned long long* o = (unsigned long long*)(g_xw + (size_t)r * COUT + tx * TC);
            #pragma unroll
            for (int j = 0; j < TC / 2; j++) o[j] = acc[i][j];
        }
    }
}

// ---------------- attention logits: ALS[n,h] = dot(XW[n, h*C:(h+1)*C], a_src[h]) ----------------
template <int COUT, int H>
__global__ void k_als(const float* __restrict__ asrc, const float* __restrict__ adst, int n) {
    int warp = (blockIdx.x * blockDim.x + threadIdx.x) >> 5;
    if (warp >= n) return;
    int lane = threadIdx.x & 31;
    constexpr int V = COUT / 32;
    const float* row = g_xw + (size_t)warp * COUT + lane * V;
    float ps = 0.f, pd = 0.f;
    #pragma unroll
    for (int v = 0; v < V; v++) {
        float xv = row[v];
        ps += xv * asrc[lane * V + v];
        pd += xv * adst[lane * V + v];
    }
    constexpr int GROUP = 32 / H;
    #pragma unroll
    for (int off = GROUP / 2; off > 0; off >>= 1) {
        ps += __shfl_xor_sync(0xffffffffu, ps, off);
        pd += __shfl_xor_sync(0xffffffffu, pd, off);
    }
    if ((lane & (GROUP - 1)) == 0) {
        int h = lane / GROUP;
        g_als[warp * H + h] = ps;
        g_ald[warp * H + h] = pd;
    }
}

// ---------------- edge aggregation: one warp per destination node ----------------
template <int COUT, int H>
__global__ void k_edge(const float* __restrict__ bias, float* __restrict__ out, int ostride, int n) {
    constexpr int V = COUT / 32;
    constexpr int C = COUT / H;
    int warp = (blockIdx.x * blockDim.x + threadIdx.x) >> 5;
    if (warp >= n) return;
    int lane = threadIdx.x & 31;
    int nid = warp;
    int start = g_roff[nid], end = g_roff[nid + 1];

    float ald[H], esf[H], emax[H];
    #pragma unroll
    for (int h = 0; h < H; h++) {
        ald[h] = g_ald[nid * H + h];
        esf[h] = leaky(g_als[nid * H + h] + ald[h]);  // self-loop logit
    }
    // pass 1: segment max (lane-strided), includes self loop
    float lmax[H];
    #pragma unroll
    for (int h = 0; h < H; h++) lmax[h] = -3.4e38f;
    for (int i = start + lane; i < end; i += 32) {
        int s = g_csr[i];
        #pragma unroll
        for (int h = 0; h < H; h++) {
            float e = leaky(g_als[s * H + h] + ald[h]);
            lmax[h] = fmaxf(lmax[h], e);
        }
    }
    #pragma unroll
    for (int h = 0; h < H; h++) {
        #pragma unroll
        for (int off = 16; off > 0; off >>= 1)
            lmax[h] = fmaxf(lmax[h], __shfl_xor_sync(0xffffffffu, lmax[h], off));
        emax[h] = fmaxf(esf[h], lmax[h]);
    }

    int myhead = (lane * V) / C;
    float acc[V];
    float denom;
    // self edge
    {
        float w = __expf(esf[myhead] - emax[myhead]);
        const float* row = g_xw + (size_t)nid * COUT + lane * V;
        if constexpr (V == 4) {
            float4 gv = *(const float4*)row;
            acc[0] = w * gv.x; acc[1] = w * gv.y; acc[2] = w * gv.z; acc[3] = w * gv.w;
        } else {
            float2 gv = *(const float2*)row;
            acc[0] = w * gv.x; acc[1] = w * gv.y;
        }
        denom = w;
    }
    // pass 2: 32-edge chunks; per-lane weight precompute, shuffle-broadcast inner loop
    for (int base = start; base < end; base += 32) {
        int m = end - base;
        if (m > 32) m = 32;
        int sl = (lane < m) ? g_csr[base + lane] : 0;
        float wl[H];
        #pragma unroll
        for (int h = 0; h < H; h++) wl[h] = 0.f;
        if (lane < m) {
            #pragma unroll
            for (int h = 0; h < H; h++) {
                float e = leaky(g_als[sl * H + h] + ald[h]);
                wl[h] = __expf(e - emax[h]);
            }
        }
        for (int j = 0; j < m; j++) {
            int s = __shfl_sync(0xffffffffu, sl, j);
            float w;
            if constexpr (H == 2) {
                float w0 = __shfl_sync(0xffffffffu, wl[0], j);
                float w1 = __shfl_sync(0xffffffffu, wl[1], j);
                w = myhead ? w1 : w0;
            } else {
                w = __shfl_sync(0xffffffffu, wl[0], j);
            }
            const float* row = g_xw + (size_t)s * COUT + lane * V;
            if constexpr (V == 4) {
                float4 gv = *(const float4*)row;
                acc[0] += w * gv.x; acc[1] += w * gv.y; acc[2] += w * gv.z; acc[3] += w * gv.w;
            } else {
                float2 gv = *(const float2*)row;
                acc[0] += w * gv.x; acc[1] += w * gv.y;
            }
            denom += w;
        }
    }
    float inv = 1.0f / (denom + 1e-16f);
    float* orow = out + (size_t)nid * ostride + lane * V;
    if constexpr (V == 4) {
        float4 o;
        o.x = fmaxf(acc[0] * inv + bias[lane * 4 + 0], 0.f);
        o.y = fmaxf(acc[1] * inv + bias[lane * 4 + 1], 0.f);
        o.z = fmaxf(acc[2] * inv + bias[lane * 4 + 2], 0.f);
        o.w = fmaxf(acc[3] * inv + bias[lane * 4 + 3], 0.f);
        *(float4*)orow = o;
    } else {
        float2 o;
        o.x = fmaxf(acc[0] * inv + bias[lane * 2 + 0], 0.f);
        o.y = fmaxf(acc[1] * inv + bias[lane * 2 + 1], 0.f);
        *(float2*)orow = o;
    }
}

// ---------------- BatchNorm (training-mode, biased stats) ----------------
template <int COUT>
__global__ void k_bnzero() {
    int c = threadIdx.x;
    g_sum[c] = 0.f;
    g_sq[c] = 0.f;
}
template <int COUT>
__global__ void k_bnstats(const float* __restrict__ out, int ostride, int n) {
    int c = threadIdx.x;
    float s = 0.f, q = 0.f;
    for (int r = blockIdx.x; r < n; r += gridDim.x) {
        float v = out[(size_t)r * ostride + c];
        s += v;
        q += v * v;
    }
    atomicAdd(&g_sum[c], s);
    atomicAdd(&g_sq[c], q);
}
template <int COUT>
__global__ void k_bnapply(float* __restrict__ out, int ostride,
                          const float* __restrict__ gam, const float* __restrict__ bet, int n) {
    int c = threadIdx.x;
    float m = g_sum[c] / (float)n;
    float var = g_sq[c] / (float)n - m * m;
    float sc = gam[c] * rsqrtf(var + 1e-5f);
    float sh = bet[c] - m * sc;
    for (int r = blockIdx.x; r < n; r += gridDim.x) {
        size_t idx = (size_t)r * ostride + c;
        out[idx] = out[idx] * sc + sh;
    }
}

// ---------------- host-side layer driver ----------------
template <int COUT, int H>
static void run_layer(const float* X, int ldx,
                      const float* W, const float* asrc, const float* adst,
                      const float* b, const float* gam, const float* bet,
                      float* outp, int ostride) {
    const int n = NN;
    size_t smem = (size_t)(128 * COUT + 64 * 128) * sizeof(float);
    cudaFuncSetAttribute(k_gemm<COUT>, cudaFuncAttributeMaxDynamicSharedMemorySize, (int)smem);
    k_gemm<COUT><<<(n + 63) / 64, 256, smem>>>(X, ldx, W, n);
    int warpblocks = (n * 32 + 255) / 256;
    k_als<COUT, H><<<warpblocks, 256>>>(asrc, adst, n);
    k_edge<COUT, H><<<warpblocks, 256>>>(b, outp, ostride, n);
    k_bnzero<COUT><<<1, COUT>>>();
    k_bnstats<COUT><<<512, COUT>>>(outp, ostride, n);
    k_bnapply<COUT><<<512, COUT>>>(outp, ostride, gam, bet, n);
}

extern "C" void kernel_launch(void* const* d_in, const int* in_sizes, int n_in,
                              void* d_out, int out_size) {
    const float* x   = (const float*)d_in[0];
    const int*   adj = (const int*)d_in[1];
    const float* W1  = (const float*)d_in[2];
    const float* as1 = (const float*)d_in[3];
    const float* ad1 = (const float*)d_in[4];
    const float* b1  = (const float*)d_in[5];
    const float* g1  = (const float*)d_in[6];
    const float* be1 = (const float*)d_in[7];
    const float* W2  = (const float*)d_in[8];
    const float* as2 = (const float*)d_in[9];
    const float* ad2 = (const float*)d_in[10];
    const float* b2  = (const float*)d_in[11];
    const float* g2  = (const float*)d_in[12];
    const float* be2 = (const float*)d_in[13];
    const float* W3  = (const float*)d_in[14];
    const float* as3 = (const float*)d_in[15];
    const float* ad3 = (const float*)d_in[16];
    const float* b3  = (const float*)d_in[17];
    const float* g3  = (const float*)d_in[18];
    const float* be3 = (const float*)d_in[19];
    float* out = (float*)d_out;

    const int* src = adj;       // adj[0, :]
    const int* dst = adj + EE;  // adj[1, :]

    // CSR build (by destination). Self loops handled inline in k_edge.
    k_zero_deg<<<(NN + 255) / 256, 256>>>();
    k_count<<<(EE + 255) / 256, 256>>>(dst, EE);
    k_scan<<<1, 1024>>>(NN);
    k_fill<<<(EE + 255) / 256, 256>>>(src, dst, EE);

    // layer 1: x[N,128] -> out[:, 0:128]
    run_layer<128, 2>(x, 128, W1, as1, ad1, b1, g1, be1, out + 0, 320);
    // layer 2: out[:,0:128] -> out[:, 128:256]
    run_layer<128, 2>(out + 0, 320, W2, as2, ad2, b2, g2, be2, out + 128, 320);
    // layer 3: out[:,128:256] -> out[:, 256:320]
    run_layer<64, 1>(out + 128, 320, W3, as3, ad3, b3, g3, be3, out + 256, 320);
}

// round 2
// speedup vs baseline: 1.0391x; 1.0391x over previous
#include <cuda_runtime.h>

#define NN 50000
#define EE 800000

// ---------------- device scratch ----------------
__device__ int   g_deg[NN];
__device__ int   g_roff[NN + 1];
__device__ int   g_cursor[NN];
__device__ int   g_csr[EE];
__device__ float g_xw[(size_t)NN * 128];
__device__ float g_als[NN * 2];
__device__ float g_ald[NN * 2];
__device__ float g_sum[128];
__device__ float g_sq[128];

// ---------------- helpers ----------------
__device__ __forceinline__ unsigned long long pack2(float a, float b) {
    unsigned long long r;
    asm("mov.b64 %0, {%1, %2};" : "=l"(r) : "f"(a), "f"(b));
    return r;
}
__device__ __forceinline__ void fma2(unsigned long long& d, unsigned long long a, unsigned long long b) {
    asm("fma.rn.f32x2 %0, %1, %2, %0;" : "+l"(d) : "l"(a), "l"(b));
}
__device__ __forceinline__ float leaky(float v) { return v > 0.f ? v : 0.2f * v; }

// ---------------- CSR build ----------------
__global__ void k_zero_deg() {
    int i = blockIdx.x * blockDim.x + threadIdx.x;
    if (i < NN) g_deg[i] = 0;
}
__global__ void k_count(const int4* __restrict__ dst4, int e4) {
    for (int i = blockIdx.x * blockDim.x + threadIdx.x; i < e4; i += gridDim.x * blockDim.x) {
        int4 d = dst4[i];
        atomicAdd(&g_deg[d.x], 1);
        atomicAdd(&g_deg[d.y], 1);
        atomicAdd(&g_deg[d.z], 1);
        atomicAdd(&g_deg[d.w], 1);
    }
}
__global__ void k_scan(int n) {
    __shared__ int part[1024];
    int tid = threadIdx.x;
    int chunk = (n + 1023) >> 10;
    int b0 = tid * chunk;
    int s = 0;
    for (int i = 0; i < chunk; i++) {
        int idx = b0 + i;
        if (idx < n) s += g_deg[idx];
    }
    part[tid] = s;
    __syncthreads();
    for (int off = 1; off < 1024; off <<= 1) {
        int v = (tid >= off) ? part[tid - off] : 0;
        __syncthreads();
        part[tid] += v;
        __syncthreads();
    }
    int run = (tid > 0) ? part[tid - 1] : 0;
    for (int i = 0; i < chunk; i++) {
        int idx = b0 + i;
        if (idx < n) {
            g_roff[idx] = run;
            g_cursor[idx] = run;
            run += g_deg[idx];
        }
    }
    if (tid == 1023) g_roff[n] = run;
}
__global__ void k_fill(const int4* __restrict__ src4, const int4* __restrict__ dst4, int e4) {
    for (int i = blockIdx.x * blockDim.x + threadIdx.x; i < e4; i += gridDim.x * blockDim.x) {
        int4 s = src4[i];
        int4 d = dst4[i];
        g_csr[atomicAdd(&g_cursor[d.x], 1)] = s.x;
        g_csr[atomicAdd(&g_cursor[d.y], 1)] = s.y;
        g_csr[atomicAdd(&g_cursor[d.z], 1)] = s.z;
        g_csr[atomicAdd(&g_cursor[d.w], 1)] = s.w;
    }
}

// ---------------- GEMM (+ optional fused BN-apply of the INPUT) ----------------
// g_xw[n, COUT] = BN(X)[n, 0:128] @ W[128, COUT]; BN'd X written back in place.
template <int COUT, bool BN>
__launch_bounds__(256, 2)
__global__ void k_gemm(float* __restrict__ X, int ldx, const float* __restrict__ W,
                       const float* __restrict__ gam, const float* __restrict__ bet, int n) {
    constexpr int K = 128;
    constexpr int TC = COUT / 16;
    extern __shared__ float sm[];
    float* Ws = sm;                  // [K][COUT]
    float* Xs = sm + K * COUT;       // [64][K]
    float* s_sc = Xs + 64 * K;       // [K]
    float* s_sh = s_sc + K;          // [K]
    int tid = threadIdx.x;
    int row0 = blockIdx.x * 64;

    if (BN) {
        if (tid < K) {
            float m = g_sum[tid] / (float)n;
            float var = g_sq[tid] / (float)n - m * m;
            float sc = gam[tid] * rsqrtf(var + 1e-5f);
            s_sc[tid] = sc;
            s_sh[tid] = bet[tid] - m * sc;
        }
        __syncthreads();
    }

    {   // load W
        const float4* W4 = (const float4*)W;
        float4* Ws4 = (float4*)Ws;
        #pragma unroll
        for (int i = tid; i < K * COUT / 4; i += 256) Ws4[i] = W4[i];
    }
    {   // load X rows (apply BN, write back)
        #pragma unroll
        for (int i = tid; i < 64 * (K / 4); i += 256) {
            int r = i >> 5;
            int kc = (i & 31) << 2;
            float4 v = make_float4(0.f, 0.f, 0.f, 0.f);
            if (row0 + r < n) {
                v = *(const float4*)(X + (size_t)(row0 + r) * ldx + kc);
                if (BN) {
                    v.x = v.x * s_sc[kc + 0] + s_sh[kc + 0];
                    v.y = v.y * s_sc[kc + 1] + s_sh[kc + 1];
                    v.z = v.z * s_sc[kc + 2] + s_sh[kc + 2];
                    v.w = v.w * s_sc[kc + 3] + s_sh[kc + 3];
                    *(float4*)(X + (size_t)(row0 + r) * ldx + kc) = v;
                }
            }
            *(float4*)(Xs + r * K + kc) = v;
        }
    }
    __syncthreads();

    int tx = tid & 15, ty = tid >> 4;
    unsigned long long acc[4][TC / 2];
    #pragma unroll
    for (int i = 0; i < 4; i++)
        #pragma unroll
        for (int j = 0; j < TC / 2; j++) acc[i][j] = 0ull;

    const float* xs0 = Xs + (ty * 4) * K;
    #pragma unroll 4
    for (int k4 = 0; k4 < K; k4 += 4) {
        float xa[4][4];
        #pragma unroll
        for (int i = 0; i < 4; i++) {
            float4 v = *(const float4*)(xs0 + i * K + k4);
            xa[i][0] = v.x; xa[i][1] = v.y; xa[i][2] = v.z; xa[i][3] = v.w;
        }
        #pragma unroll
        for (int kk = 0; kk < 4; kk++) {
            unsigned long long xp[4];
            #pragma unroll
            for (int i = 0; i < 4; i++) xp[i] = pack2(xa[i][kk], xa[i][kk]);
            const longlong2* wr = (const longlong2*)(Ws + (k4 + kk) * COUT + tx * TC);
            #pragma unroll
            for (int jj = 0; jj < TC / 4; jj++) {
                longlong2 wv = wr[jj];
                #pragma unroll
                for (int i = 0; i < 4; i++) {
                    fma2(acc[i][2 * jj], xp[i], (unsigned long long)wv.x);
                    fma2(acc[i][2 * jj + 1], xp[i], (unsigned long long)wv.y);
                }
            }
        }
    }
    #pragma unroll
    for (int i = 0; i < 4; i++) {
        int r = row0 + ty * 4 + i;
        if (r < n) {
            unsigned long long* o = (unsigned long long*)(g_xw + (size_t)r * COUT + tx * TC);
            #pragma unroll
            for (int j = 0; j < TC / 2; j++) o[j] = acc[i][j];
        }
    }
}

// ---------------- attention logits (+ zero BN stat accumulators) ----------------
template <int COUT, int H>
__global__ void k_als(const float* __restrict__ asrc, const float* __restrict__ adst, int n) {
    if (blockIdx.x == 0 && threadIdx.x < 128) {
        g_sum[threadIdx.x] = 0.f;
        g_sq[threadIdx.x] = 0.f;
    }
    int warp = (blockIdx.x * blockDim.x + threadIdx.x) >> 5;
    if (warp >= n) return;
    int lane = threadIdx.x & 31;
    constexpr int V = COUT / 32;
    const float* row = g_xw + (size_t)warp * COUT + lane * V;
    float ps = 0.f, pd = 0.f;
    #pragma unroll
    for (int v = 0; v < V; v++) {
        float xv = row[v];
        ps += xv * asrc[lane * V + v];
        pd += xv * adst[lane * V + v];
    }
    constexpr int GROUP = 32 / H;
    #pragma unroll
    for (int off = GROUP / 2; off > 0; off >>= 1) {
        ps += __shfl_xor_sync(0xffffffffu, ps, off);
        pd += __shfl_xor_sync(0xffffffffu, pd, off);
    }
    if ((lane & (GROUP - 1)) == 0) {
        int h = lane / GROUP;
        g_als[warp * H + h] = ps;
        g_ald[warp * H + h] = pd;
    }
}

// ---------------- single-pass edge aggregation + relu + fused BN stats ----------------
template <int COUT, int H>
__launch_bounds__(256)
__global__ void k_edge(const float* __restrict__ bias, float* __restrict__ out, int ostride, int n) {
    constexpr int V = COUT / 32;
    __shared__ float s_sum[COUT];
    __shared__ float s_sq[COUT];
    for (int i = threadIdx.x; i < COUT; i += 256) { s_sum[i] = 0.f; s_sq[i] = 0.f; }
    __syncthreads();

    int warp = (blockIdx.x * blockDim.x + threadIdx.x) >> 5;
    int lane = threadIdx.x & 31;
    if (warp < n) {
        int nid = warp;
        int start = g_roff[nid], end = g_roff[nid + 1];
        int myhead = (H == 2) ? (lane >> 4) : 0;

        float ald[H];
        #pragma unroll
        for (int h = 0; h < H; h++) ald[h] = g_ald[nid * H + h];

        float acc[V];
        float denom;
        {   // self loop
            float w = __expf(leaky(g_als[nid * H + myhead] + ald[myhead]));
            const float* row = g_xw + (size_t)nid * COUT + lane * V;
            #pragma unroll
            for (int v = 0; v < V; v++) acc[v] = w * row[v];
            denom = w;
        }

        for (int base = start; base < end; base += 32) {
            int m = end - base;
            if (m > 32) m = 32;
            int sl = (lane < m) ? g_csr[base + lane] : 0;
            float w0l = 0.f, w1l = 0.f;
            if (lane < m) {
                w0l = __expf(leaky(g_als[sl * H + 0] + ald[0]));
                if (H == 2) w1l = __expf(leaky(g_als[sl * H + 1] + ald[1]));
            }
            int j = 0;
            for (; j + 4 <= m; j += 4) {
                int s0 = __shfl_sync(0xffffffffu, sl, j + 0);
                int s1 = __shfl_sync(0xffffffffu, sl, j + 1);
                int s2 = __shfl_sync(0xffffffffu, sl, j + 2);
                int s3 = __shfl_sync(0xffffffffu, sl, j + 3);
                float w0, w1, w2, w3;
                if (H == 2) {
                    float a0 = __shfl_sync(0xffffffffu, w0l, j + 0), b0 = __shfl_sync(0xffffffffu, w1l, j + 0);
                    float a1 = __shfl_sync(0xffffffffu, w0l, j + 1), b1 = __shfl_sync(0xffffffffu, w1l, j + 1);
                    float a2 = __shfl_sync(0xffffffffu, w0l, j + 2), b2 = __shfl_sync(0xffffffffu, w1l, j + 2);
                    float a3 = __shfl_sync(0xffffffffu, w0l, j + 3), b3 = __shfl_sync(0xffffffffu, w1l, j + 3);
                    w0 = myhead ? b0 : a0; w1 = myhead ? b1 : a1;
                    w2 = myhead ? b2 : a2; w3 = myhead ? b3 : a3;
                } else {
                    w0 = __shfl_sync(0xffffffffu, w0l, j + 0);
                    w1 = __shfl_sync(0xffffffffu, w0l, j + 1);
                    w2 = __shfl_sync(0xffffffffu, w0l, j + 2);
                    w3 = __shfl_sync(0xffffffffu, w0l, j + 3);
                }
                if (V == 4) {
                    float4 r0 = ((const float4*)(g_xw + (size_t)s0 * COUT))[lane];
                    float4 r1 = ((const float4*)(g_xw + (size_t)s1 * COUT))[lane];
                    float4 r2 = ((const float4*)(g_xw + (size_t)s2 * COUT))[lane];
                    float4 r3 = ((const float4*)(g_xw + (size_t)s3 * COUT))[lane];
                    acc[0] += w0 * r0.x + w1 * r1.x + w2 * r2.x + w3 * r3.x;
                    acc[1] += w0 * r0.y + w1 * r1.y + w2 * r2.y + w3 * r3.y;
                    acc[2] += w0 * r0.z + w1 * r1.z + w2 * r2.z + w3 * r3.z;
                    acc[3] += w0 * r0.w + w1 * r1.w + w2 * r2.w + w3 * r3.w;
                } else {
                    float2 r0 = ((const float2*)(g_xw + (size_t)s0 * COUT))[lane];
                    float2 r1 = ((const float2*)(g_xw + (size_t)s1 * COUT))[lane];
                    float2 r2 = ((const float2*)(g_xw + (size_t)s2 * COUT))[lane];
                    float2 r3 = ((const float2*)(g_xw + (size_t)s3 * COUT))[lane];
                    acc[0] += w0 * r0.x + w1 * r1.x + w2 * r2.x + w3 * r3.x;
                    acc[1] += w0 * r0.y + w1 * r1.y + w2 * r2.y + w3 * r3.y;
                }
                denom += (w0 + w1) + (w2 + w3);
            }
            for (; j < m; j++) {
                int s = __shfl_sync(0xffffffffu, sl, j);
                float w;
                if (H == 2) {
                    float a = __shfl_sync(0xffffffffu, w0l, j);
                    float b = __shfl_sync(0xffffffffu, w1l, j);
                    w = myhead ? b : a;
                } else {
                    w = __shfl_sync(0xffffffffu, w0l, j);
                }
                const float* row = g_xw + (size_t)s * COUT + lane * V;
                #pragma unroll
                for (int v = 0; v < V; v++) acc[v] += w * row[v];
                denom += w;
            }
        }

        float inv = 1.0f / (denom + 1e-16f);
        float ov[V];
        #pragma unroll
        for (int v = 0; v < V; v++)
            ov[v] = fmaxf(acc[v] * inv + bias[lane * V + v], 0.f);

        float* orow = out + (size_t)nid * ostride + lane * V;
        if (V == 4) *(float4*)orow = make_float4(ov[0], ov[1], ov[2], ov[3]);
        else        *(float2*)orow = make_float2(ov[0], ov[1]);

        #pragma unroll
        for (int v = 0; v < V; v++) {
            atomicAdd(&s_sum[lane * V + v], ov[v]);
            atomicAdd(&s_sq[lane * V + v], ov[v] * ov[v]);
        }
    }
    __syncthreads();
    for (int i = threadIdx.x; i < COUT; i += 256) {
        atomicAdd(&g_sum[i], s_sum[i]);
        atomicAdd(&g_sq[i], s_sq[i]);
    }
}

// ---------------- final BN apply (layer 3 slab only) ----------------
__global__ void k_bnapply3(float* __restrict__ out, int ostride,
                           const float* __restrict__ gam, const float* __restrict__ bet, int n) {
    int c = threadIdx.x;  // 64
    float m = g_sum[c] / (float)n;
    float var = g_sq[c] / (float)n - m * m;
    float sc = gam[c] * rsqrtf(var + 1e-5f);
    float sh = bet[c] - m * sc;
    for (int r = blockIdx.x; r < n; r += gridDim.x) {
        size_t idx = (size_t)r * ostride + c;
        out[idx] = out[idx] * sc + sh;
    }
}

// ---------------- host driver ----------------
template <int COUT, int H, bool BN>
static void run_layer(float* X, int ldx, const float* W,
                      const float* asrc, const float* adst, const float* b,
                      const float* gam_prev, const float* bet_prev,
                      float* outp, int ostride) {
    const int n = NN;
    size_t smem = (size_t)(128 * COUT + 64 * 128 + 256) * sizeof(float);
    cudaFuncSetAttribute(k_gemm<COUT, BN>, cudaFuncAttributeMaxDynamicSharedMemorySize, (int)smem);
    k_gemm<COUT, BN><<<(n + 63) / 64, 256, smem>>>(X, ldx, W, gam_prev, bet_prev, n);
    int warpblocks = (n * 32 + 255) / 256;
    k_als<COUT, H><<<warpblocks, 256>>>(asrc, adst, n);
    k_edge<COUT, H><<<warpblocks, 256>>>(b, outp, ostride, n);
}

extern "C" void kernel_launch(void* const* d_in, const int* in_sizes, int n_in,
                              void* d_out, int out_size) {
    float*       x   = (float*)d_in[0];
    const int*   adj = (const int*)d_in[1];
    const float* W1  = (const float*)d_in[2];
    const float* as1 = (const float*)d_in[3];
    const float* ad1 = (const float*)d_in[4];
    const float* b1  = (const float*)d_in[5];
    const float* g1  = (const float*)d_in[6];
    const float* be1 = (const float*)d_in[7];
    const float* W2  = (const float*)d_in[8];
    const float* as2 = (const float*)d_in[9];
    const float* ad2 = (const float*)d_in[10];
    const float* b2  = (const float*)d_in[11];
    const float* g2  = (const float*)d_in[12];
    const float* be2 = (const float*)d_in[13];
    const float* W3  = (const float*)d_in[14];
    const float* as3 = (const float*)d_in[15];
    const float* ad3 = (const float*)d_in[16];
    const float* b3  = (const float*)d_in[17];
    const float* g3  = (const float*)d_in[18];
    const float* be3 = (const float*)d_in[19];
    float* out = (float*)d_out;

    const int4* src4 = (const int4*)adj;
    const int4* dst4 = (const int4*)(adj + EE);

    k_zero_deg<<<(NN + 255) / 256, 256>>>();
    k_count<<<(EE / 4 + 255) / 256, 256>>>(dst4, EE / 4);
    k_scan<<<1, 1024>>>(NN);
    k_fill<<<(EE / 4 + 255) / 256, 256>>>(src4, dst4, EE / 4);

    // layer 1: x (no input BN) -> out[:,0:128] (pre-BN relu values + stats)
    run_layer<128, 2, false>(x, 128, W1, as1, ad1, b1, nullptr, nullptr, out + 0, 320);
    // layer 2: GEMM BN-applies layer-1 stats to out[:,0:128] in place
    run_layer<128, 2, true>(out + 0, 320, W2, as2, ad2, b2, g1, be1, out + 128, 320);
    // layer 3: GEMM BN-applies layer-2 stats to out[:,128:256] in place
    run_layer<64, 1, true>(out + 128, 320, W3, as3, ad3, b3, g2, be2, out + 256, 320);
    // final BN on layer-3 slab
    k_bnapply3<<<512, 64>>>(out + 256, 320, g3, be3, NN);
}